// round 16
// baseline (speedup 1.0000x reference)
#include <cuda_runtime.h>
#include <math.h>

#define BB 16
#define NN 2048
#define MM 32
#define PP 48
#define TT 5
#define CC (PP*TT)   // 240

#define APB 4            // atoms per block (smaller block -> more blocks/SM)
#define TH1 (APB*PP)     // 192 threads = 6 warps; phase A uses warps 0..3
#define NPB 4            // n-columns per norm block

// Per-atom BN partials: g_part[atom] = {sum, sumsq} over 240 channels.
// Unconditionally overwritten every launch -> deterministic, no zeroing.
__device__ float2 g_part[BB * NN];

__device__ __forceinline__ float ex2_fast(float x) {
    float r; asm("ex2.approx.f32 %0, %1;" : "=f"(r) : "f"(x)); return r;
}
__device__ __forceinline__ float sqrt_fast(float x) {
    float r; asm("sqrt.approx.f32 %0, %1;" : "=f"(r) : "f"(x)); return r;
}

// ---------------------------------------------------------------------------
// Kernel 1: radial symmetry functions + BN partials (R6 structure; only the
// block geometry changed: APB 8->4, TH 384->192, natural registers).
// At ~48 regs: 7 blocks/SM = 1344 resident threads (~66% occ) vs 3x384=1152.
// ---------------------------------------------------------------------------
__global__ __launch_bounds__(TH1)
void rsf_kernel(const float* __restrict__ X,
                const float* __restrict__ rc,
                const float* __restrict__ rs,
                const float* __restrict__ re,
                const int*   __restrict__ Nbrs,
                const int*   __restrict__ NbrsZ,
                float*       __restrict__ out)
{
    __shared__ float2 sRT[APB][MM];
    __shared__ int    sCnt[APB];
    __shared__ float2 sPart[TH1];

    const int tid  = threadIdx.x;
    const int warp = tid >> 5;
    const int lane = tid & 31;
    const int baseAtom = blockIdx.x * APB;      // atom = b*N + n

    // ---------------- Phase A: one warp per atom (warps 0..3) ----------
    if (warp < APB) {
        const int atom = baseAtom + warp;
        const int b    = atom >> 11;
        const float* xp = X + atom * 3;
        const float x0 = xp[0], x1 = xp[1], x2 = xp[2];

        const int nb = Nbrs [atom * MM + lane];
        const int z  = NbrsZ[atom * MM + lane];
        const float* np_ = X + ((b << 11) + nb) * 3;
        const float dx = np_[0] - x0;
        const float dy = np_[1] - x1;
        const float dz = np_[2] - x2;
        const float R  = sqrt_fast(dx*dx + dy*dy + dz*dz);

        int t = -1;
        if      (z == 1)  t = 0;
        else if (z == 6)  t = 1;
        else if (z == 7)  t = 2;
        else if (z == 8)  t = 3;
        else if (z == 16) t = 4;

        const unsigned mask = __ballot_sync(0xffffffffu, t >= 0);
        if (t >= 0) {
            const int pos = __popc(mask & ((1u << lane) - 1u));
            sRT[warp][pos] = make_float2(R, __int_as_float(t));
        }
        if (lane == 0) sCnt[warp] = __popc(mask);
    }
    __syncthreads();

    // ---------------- Phase B: 192 threads, thread=(g,j) ----------------
    const int g = tid / PP;        // atom within block
    const int j = tid % PP;        // radial index p
    const int atom = baseAtom + g;

    const float myrc  = rc[j];
    const float myrs  = rs[j];
    const float nre2  = -re[j] * 1.44269504088896f;  // fold log2(e)
    const float pi_rc = 3.14159265358979f / myrc;
    const float2* rt  = sRT[g];
    const int total   = sCnt[g];

    float acc[TT];
    #pragma unroll
    for (int tt = 0; tt < TT; tt++) acc[tt] = 0.0f;

    int m = 0;
    for (; m + 2 <= total; m += 2) {
        const float2 a0 = rt[m];
        const float2 a1 = rt[m + 1];
        const float R0 = a0.x, R1 = a1.x;
        const int   t0 = __float_as_int(a0.y);
        const int   t1 = __float_as_int(a1.y);
        const float d0 = R0 - myrs;
        const float d1 = R1 - myrs;
        const float e0 = ex2_fast(nre2 * d0 * d0);
        const float e1 = ex2_fast(nre2 * d1 * d1);
        const float c0 = __cosf(R0 * pi_rc);
        const float c1 = __cosf(R1 * pi_rc);
        float f0 = fmaf(c0, 0.5f, 0.5f);
        float f1 = fmaf(c1, 0.5f, 0.5f);
        f0 = (R0 <= myrc) ? f0 : 0.0f;
        f1 = (R1 <= myrc) ? f1 : 0.0f;
        const float v0 = e0 * f0;
        const float v1 = e1 * f1;
        #pragma unroll
        for (int tt = 0; tt < TT; tt++) {
            if (t0 == tt) acc[tt] += v0;
            if (t1 == tt) acc[tt] += v1;
        }
    }
    if (m < total) {
        const float2 a0 = rt[m];
        const float R0 = a0.x;
        const int   t0 = __float_as_int(a0.y);
        const float d0 = R0 - myrs;
        const float e0 = ex2_fast(nre2 * d0 * d0);
        const float c0 = __cosf(R0 * pi_rc);
        float f0 = fmaf(c0, 0.5f, 0.5f);
        f0 = (R0 <= myrc) ? f0 : 0.0f;
        const float v0 = e0 * f0;
        #pragma unroll
        for (int tt = 0; tt < TT; tt++) {
            if (t0 == tt) acc[tt] += v0;
        }
    }

    float s = 0.0f, s2 = 0.0f;
    {
        float* op = out + (size_t)atom * CC;
        #pragma unroll
        for (int tt = 0; tt < TT; tt++) {
            const float a = acc[tt];
            op[tt * PP + j] = a;
            s  += a;
            s2 = fmaf(a, a, s2);
        }
    }
    sPart[tid] = make_float2(s, s2);
    __syncthreads();

    // ---------------- Phase C: per-atom reduce of (s,s2) ----------------
    if (warp < APB) {
        const float2 p0 = sPart[warp * PP + lane];
        float s  = p0.x;
        float s2 = p0.y;
        if (lane < PP - 32) {
            const float2 p1 = sPart[warp * PP + 32 + lane];
            s  += p1.x;
            s2 += p1.y;
        }
        #pragma unroll
        for (int o = 16; o > 0; o >>= 1) {
            s  += __shfl_down_sync(0xffffffffu, s,  o);
            s2 += __shfl_down_sync(0xffffffffu, s2, o);
        }
        if (lane == 0) g_part[baseAtom + warp] = make_float2(s, s2);
    }
}

// ---------------------------------------------------------------------------
// Kernel 2: BatchNorm normalize (R14 version verbatim). 512 blocks x 256;
// warps 0..3 compute stats for 4 n-columns in parallel, then all threads
// stream 4 x 960 float4.
// ---------------------------------------------------------------------------
__global__ __launch_bounds__(256)
void norm_kernel(float4* __restrict__ out4)
{
    const int n0  = blockIdx.x * NPB;
    const int tid = threadIdx.x;
    const int warp = tid >> 5;
    const int lane = tid & 31;

    __shared__ float2 sStat[NPB];    // {mean, inv} per n

    if (warp < NPB) {
        const int n = n0 + warp;
        float s = 0.0f, s2 = 0.0f;
        if (lane < BB) {
            const float2 p = g_part[lane * NN + n];
            s = p.x; s2 = p.y;
        }
        #pragma unroll
        for (int o = 16; o > 0; o >>= 1) {
            s  += __shfl_down_sync(0xffffffffu, s,  o);
            s2 += __shfl_down_sync(0xffffffffu, s2, o);
        }
        if (lane == 0) {
            const float invn = 1.0f / (float)(BB * CC);
            const float mean = s * invn;
            float var = s2 * invn - mean * mean;
            var = fmaxf(var, 0.0f);
            sStat[warp] = make_float2(mean, rsqrtf(var + 1e-5f));
        }
    }
    __syncthreads();

    #pragma unroll
    for (int nl = 0; nl < NPB; nl++) {
        const int n = n0 + nl;
        const float mean = sStat[nl].x;
        const float inv  = sStat[nl].y;

        float4 v[4];
        size_t idx[4];
        #pragma unroll
        for (int r = 0; r < 4; r++) {
            const int i = r * 256 + tid;
            if (i < 960) {
                const int b  = i / 60;
                const int c4 = i % 60;
                idx[r] = (size_t)(b * NN + n) * (CC / 4) + c4;
                v[r] = out4[idx[r]];
            }
        }
        #pragma unroll
        for (int r = 0; r < 4; r++) {
            const int i = r * 256 + tid;
            if (i < 960) {
                v[r].x = (v[r].x - mean) * inv;
                v[r].y = (v[r].y - mean) * inv;
                v[r].z = (v[r].z - mean) * inv;
                v[r].w = (v[r].w - mean) * inv;
                out4[idx[r]] = v[r];
            }
        }
    }
}

// ---------------------------------------------------------------------------
extern "C" void kernel_launch(void* const* d_in, const int* in_sizes, int n_in,
                              void* d_out, int out_size)
{
    const float* X     = (const float*)d_in[0];
    const float* rc    = (const float*)d_in[1];
    const float* rs    = (const float*)d_in[2];
    const float* re    = (const float*)d_in[3];
    const int*   Nbrs  = (const int*)  d_in[4];
    const int*   NbrsZ = (const int*)  d_in[5];

    const int nAtoms = BB * NN;                 // 32768
    rsf_kernel<<<nAtoms / APB, TH1>>>(X, rc, rs, re, Nbrs, NbrsZ, (float*)d_out);
    norm_kernel<<<NN / NPB, 256>>>((float4*)d_out);
}